// round 14
// baseline (speedup 1.0000x reference)
#include <cuda_runtime.h>
#include <cuda_bf16.h>
#include <cstdint>

#define KDIM 512
#define DDIM 1024
#define KK (KDIM*KDIM)
#define KD (KDIM*DDIM)
#define LMBDA 1000.0f
#define NITER 20

// ---------------- device scratch ----------------
__device__ __align__(16) float g_Ga[KK];
__device__ __align__(16) float g_Gb[KK];
__device__ __align__(16) float g_B0[KK];
__device__ __align__(16) float g_B1[KK];
__device__ __align__(16) float g_mask[2*KK];
__device__ __align__(16) float g_invM[2*KK];
__device__ __align__(16) float g_R[2*KK];
__device__ __align__(16) float g_P[2*KK];
__device__ __align__(16) float g_Sp[12*KK];   // phase1: 12 partials; phase0: 3 used
__device__ float g_rz[2*KDIM];
__device__ float g_smax;
// bf16 3-way splits
__device__ __align__(16) __nv_bfloat16 g_Pb[3*2*KK];   // [split][dir][row][k]
__device__ __align__(16) __nv_bfloat16 g_G3[3*2*KK];   // [split][dir][n][k]
__device__ __align__(16) __nv_bfloat16 g_Xt[3*KD];     // [split][m=512][d=1024]
__device__ __align__(16) __nv_bfloat16 g_Yt[3*KD];

// product list covering x*y to ~2^-27: (0,0),(0,1),(1,0),(1,1),(0,2),(2,0)
__constant__ int c_pa[6] = {0,0,1,1,0,2};
__constant__ int c_pb[6] = {0,1,0,1,2,0};
// phase0 3-product halves
__constant__ int c_pa0[2][3] = {{0,0,1},{1,0,2}};
__constant__ int c_pb0[2][3] = {{0,1,0},{1,2,0}};

// ---------------- helpers ----------------
__device__ __forceinline__ uint32_t smem_u32(const void* p) {
    uint32_t a;
    asm("{ .reg .u64 t; cvta.to.shared.u64 t, %1; cvt.u32.u64 %0, t; }" : "=r"(a) : "l"(p));
    return a;
}
__device__ __forceinline__ void cp16(uint32_t dst, const void* src) {
    asm volatile("cp.async.cg.shared.global [%0], [%1], 16;" :: "r"(dst), "l"(src));
}
#define CP_COMMIT() asm volatile("cp.async.commit_group;" ::: "memory")
#define CP_WAIT1()  asm volatile("cp.async.wait_group 1;" ::: "memory")
#define CP_WAIT0()  asm volatile("cp.async.wait_group 0;" ::: "memory")

__device__ __forceinline__ void ldm_x4(uint32_t* r, uint32_t addr) {
    asm volatile("ldmatrix.sync.aligned.m8n8.x4.shared.b16 {%0,%1,%2,%3}, [%4];"
        : "=r"(r[0]), "=r"(r[1]), "=r"(r[2]), "=r"(r[3]) : "r"(addr));
}
__device__ __forceinline__ void mma16816(float* d, const uint32_t* a, uint32_t b0, uint32_t b1) {
    asm volatile(
        "mma.sync.aligned.m16n8k16.row.col.f32.bf16.bf16.f32 "
        "{%0,%1,%2,%3}, {%4,%5,%6,%7}, {%8,%9}, {%0,%1,%2,%3};"
        : "+f"(d[0]), "+f"(d[1]), "+f"(d[2]), "+f"(d[3])
        : "r"(a[0]), "r"(a[1]), "r"(a[2]), "r"(a[3]), "r"(b0), "r"(b1));
}

__device__ __forceinline__ float blockReduce256(float v, float* sh) {
    #pragma unroll
    for (int o = 16; o > 0; o >>= 1) v += __shfl_xor_sync(0xffffffffu, v, o);
    int w = threadIdx.x >> 5;
    if ((threadIdx.x & 31) == 0) sh[w] = v;
    __syncthreads();
    if (threadIdx.x < 32) {
        float r = (threadIdx.x < 8) ? sh[threadIdx.x] : 0.f;
        #pragma unroll
        for (int o = 4; o > 0; o >>= 1) r += __shfl_xor_sync(0xffffffffu, r, o);
        if (threadIdx.x == 0) sh[0] = r;
    }
    __syncthreads();
    float out = sh[0];
    __syncthreads();
    return out;
}

__device__ __forceinline__ void split3(float x, __nv_bfloat16& a, __nv_bfloat16& b, __nv_bfloat16& c) {
    a = __float2bfloat16_rn(x);
    float r = x - __bfloat162float(a);
    b = __float2bfloat16_rn(r);
    r -= __bfloat162float(b);
    c = __float2bfloat16_rn(r);
}

// ---------------- K1: joint max eigenvalue ----------------
__global__ void kmax(const float* __restrict__ ea, const float* __restrict__ eb) {
    __shared__ float sm[256];
    int t = threadIdx.x;
    float m = 0.f;
    for (int i = t; i < KDIM; i += 256) { m = fmaxf(m, ea[i]); m = fmaxf(m, eb[i]); }
    sm[t] = m; __syncthreads();
    for (int s = 128; s > 0; s >>= 1) { if (t < s) sm[t] = fmaxf(sm[t], sm[t + s]); __syncthreads(); }
    if (t == 0) g_smax = sm[0];
}

// ---------------- K2: resolvent masks ----------------
__global__ void kmask(const float* __restrict__ ea, const float* __restrict__ eb) {
    int idx = blockIdx.x * blockDim.x + threadIdx.x;
    if (idx >= 2 * KK) return;
    int d = idx / KK;
    int rem = idx - d * KK;
    int r = rem >> 9, c = rem & (KDIM - 1);
    float s = g_smax;
    const float* er = (d == 0) ? eb : ea;
    const float* ec = (d == 0) ? ea : eb;
    float gb = er[r] / s, ga = ec[c] / s;
    float gb2 = gb * gb + 1.f, ga2 = ga * ga + 1.f;
    float mre = gb / gb2 - ga / ga2;
    float mim = 1.f / gb2 - 1.f / ga2;
    g_mask[idx] = mre * mre + mim * mim;
}

// ---------------- K3: transpose + 3-way split of descriptors ----------------
__global__ void __launch_bounds__(256) ktrs(const float* __restrict__ X,
                                            const float* __restrict__ Y) {
    const float* src = blockIdx.z ? Y : X;
    __nv_bfloat16* dst = blockIdx.z ? g_Yt : g_Xt;
    __shared__ float t[32][33];
    int c0 = blockIdx.x * 32, r0 = blockIdx.y * 32;
    int tx = threadIdx.x & 31, ty = threadIdx.x >> 5;
    #pragma unroll
    for (int i = 0; i < 32; i += 8)
        t[ty + i][tx] = src[(size_t)(r0 + ty + i) * KDIM + c0 + tx];
    __syncthreads();
    #pragma unroll
    for (int i = 0; i < 32; i += 8) {
        int m = c0 + ty + i;
        int dcol = r0 + tx;
        float v = t[tx][ty + i];
        __nv_bfloat16 a, b, c;
        split3(v, a, b, c);
        size_t o = (size_t)m * DDIM + dcol;
        dst[o] = a; dst[KD + o] = b; dst[2 * KD + o] = c;
    }
}

// ---------------- K4: bf16-split HMMA GEMM, 128x64 tiles, 256 thr, 2-stage ----------------
// phase 0: grid (4,8,8): z&3 -> {Ga,Gb,B0,(skip)}, z>>2 -> 3-product half; K=3*1024
//          Ga/Gb tiles with n0 >= m0+128 skipped (mirrored in kfold)
// phase 1: grid (4,8,12): z&1 -> dir, z>>1 -> product j (0..5); K=512; writes g_Sp[(j*2+dir)]
__global__ void __launch_bounds__(256, 3) gemm_mma(int phase) {
    extern __shared__ __align__(16) uint8_t dynsm[];
    int tid = threadIdx.x, lane = tid & 31, warp = tid >> 5;
    int m0 = blockIdx.x * 128, n0 = blockIdx.y * 64, z = blockIdx.z;

    const __nv_bfloat16* Aseg[3];
    const __nv_bfloat16* Bseg[3];
    int ldk, nch, cpsh;
    float* Cp;
    if (phase == 0) {
        int outz = z & 3, h = z >> 2;
        if (outz == 3) return;                     // B1 = B0^T (ktrB1)
        if (outz < 2 && n0 >= m0 + 128) return;    // symmetric: keep tiles touching lower tri
        const __nv_bfloat16* L  = (outz == 0) ? g_Xt : g_Yt;
        const __nv_bfloat16* Rt = (outz == 1) ? g_Yt : g_Xt;
        #pragma unroll
        for (int s = 0; s < 3; s++) {
            Aseg[s] = L  + (size_t)c_pa0[h][s] * KD;
            Bseg[s] = Rt + (size_t)c_pb0[h][s] * KD;
        }
        ldk = DDIM; nch = 48; cpsh = 4;
        float* prim[3] = { g_Ga, g_Gb, g_B0 };
        Cp = h ? (g_Sp + (size_t)outz * KK) : prim[outz];
    } else {
        int dir = z & 1, j = z >> 1;               // product j: single K=512 segment
        Aseg[0] = g_Pb + (size_t)c_pa[j] * 2 * KK + (size_t)dir * KK;
        Bseg[0] = g_G3 + (size_t)c_pb[j] * 2 * KK + (size_t)dir * KK;
        Aseg[1] = Aseg[0]; Aseg[2] = Aseg[0];
        Bseg[1] = Bseg[0]; Bseg[2] = Bseg[0];
        ldk = KDIM; nch = 8; cpsh = 3;
        Cp = g_Sp + (size_t)(j * 2 + dir) * KK;
    }

    uint32_t sb = smem_u32(dynsm);
    // stage = A(128x144B) + B(64x144B) = 27648B; 2 stages = 55296B
    uint32_t aAdr[2] = { sb, sb + 27648u };
    uint32_t bAdr[2] = { sb + 18432u, sb + 27648u + 18432u };

    int rowA = tid >> 1, uqA = (tid & 1) * 4;   // A: 128 rows, 4 x 16B units/thread
    int rowB = tid >> 2, uqB = (tid & 3) * 2;   // B: 64 rows, 2 x 16B units/thread

    auto issue = [&](int c, int buf) {
        int seg = c >> cpsh;
        int koff = (c - (seg << cpsh)) * 64;
        const __nv_bfloat16* As = Aseg[seg] + (size_t)(m0 + rowA) * ldk + koff + uqA * 8;
        const __nv_bfloat16* Bs = Bseg[seg] + (size_t)(n0 + rowB) * ldk + koff + uqB * 8;
        uint32_t soA = (uint32_t)(rowA * 144 + uqA * 16);
        uint32_t soB = (uint32_t)(rowB * 144 + uqB * 16);
        cp16(aAdr[buf] + soA,      As);
        cp16(aAdr[buf] + soA + 16, As + 8);
        cp16(aAdr[buf] + soA + 32, As + 16);
        cp16(aAdr[buf] + soA + 48, As + 24);
        cp16(bAdr[buf] + soB,      Bs);
        cp16(bAdr[buf] + soB + 16, Bs + 8);
        CP_COMMIT();
    };

    // 8 warps: 4 m-slices (32 rows) x 2 n-slices (32 cols) — R8's proven warp tile
    float acc[2][4][4] = {};
    int wm = (warp & 3) * 32, wn = (warp >> 2) * 32;
    int lrow = lane & 15, lhalf = lane >> 4;

    issue(0, 0);
    for (int c = 0; c < nch; c++) {
        int buf = c & 1;
        if (c + 1 < nch) { issue(c + 1, buf ^ 1); CP_WAIT1(); }
        else CP_WAIT0();
        __syncthreads();

        uint32_t aA = aAdr[buf] + (uint32_t)((wm + lrow) * 144 + lhalf * 16);
        uint32_t aB = bAdr[buf] + (uint32_t)((wn + lrow) * 144 + lhalf * 16);
        #pragma unroll
        for (int s = 0; s < 4; s++) {
            uint32_t a[2][4], bq[2][4];
            uint32_t ko = (uint32_t)(s * 32);
            ldm_x4(a[0],  aA + ko);
            ldm_x4(a[1],  aA + 16 * 144 + ko);
            ldm_x4(bq[0], aB + ko);
            ldm_x4(bq[1], aB + 16 * 144 + ko);
            #pragma unroll
            for (int mh = 0; mh < 2; mh++)
                #pragma unroll
                for (int nf = 0; nf < 4; nf++) {
                    int nh = nf >> 1, f = nf & 1;
                    mma16816(acc[mh][nf], a[mh], bq[nh][f], bq[nh][f + 2]);
                }
        }
        __syncthreads();
    }

    // epilogue: pure store of partial tile
    int rr = m0 + wm + (lane >> 2);
    int cc0 = n0 + wn + (lane & 3) * 2;
    #pragma unroll
    for (int mh = 0; mh < 2; mh++) {
        #pragma unroll
        for (int nf = 0; nf < 4; nf++) {
            int r = rr + mh * 16;
            int cc = cc0 + nf * 8;
            *(float2*)&Cp[(size_t)r * KDIM + cc] =
                make_float2(acc[mh][nf][0], acc[mh][nf][1]);
            *(float2*)&Cp[(size_t)(r + 8) * KDIM + cc] =
                make_float2(acc[mh][nf][2], acc[mh][nf][3]);
        }
    }
}

// ---------------- K4b: fold phase-0 partials (Ga/Gb mirrored, B0 full) ----------------
__global__ void kfold() {
    int i = blockIdx.x * blockDim.x + threadIdx.x;
    if (i >= KK) return;
    int r = i >> 9, c = i & (KDIM - 1);
    if (r >= c) {
        float va = g_Ga[i] + g_Sp[i];
        float vb = g_Gb[i] + g_Sp[KK + i];
        int it = c * KDIM + r;
        g_Ga[i] = va; g_Ga[it] = va;
        g_Gb[i] = vb; g_Gb[it] = vb;
    }
    g_B0[i] += g_Sp[2 * KK + i];
}

// ---------------- K4c: B1 = B0^T (tiled transpose) ----------------
__global__ void __launch_bounds__(256) ktrB1() {
    __shared__ float t[32][33];
    int c0 = blockIdx.x * 32, r0 = blockIdx.y * 32;
    int tx = threadIdx.x & 31, ty = threadIdx.x >> 5;
    #pragma unroll
    for (int i = 0; i < 32; i += 8)
        t[ty + i][tx] = g_B0[(size_t)(r0 + ty + i) * KDIM + c0 + tx];
    __syncthreads();
    #pragma unroll
    for (int i = 0; i < 32; i += 8)
        g_B1[(size_t)(c0 + ty + i) * KDIM + r0 + tx] = t[tx][ty + i];
}

// ---------------- K5: 3-way bf16 split of G ----------------
__global__ void ksplitG() {
    int idx = blockIdx.x * blockDim.x + threadIdx.x;
    if (idx >= 2 * KK) return;
    float v = (idx < KK) ? g_Ga[idx] : g_Gb[idx - KK];
    __nv_bfloat16 a, b, c;
    split3(v, a, b, c);
    g_G3[idx] = a;
    g_G3[2 * KK + idx] = b;
    g_G3[4 * KK + idx] = c;
}

// ---------------- K6: PCG init ----------------
__global__ void __launch_bounds__(256) kinit(float* __restrict__ out) {
    __shared__ float sh[8];
    int blk = blockIdx.x;
    int dir = blk >> 9, row = blk & 511;
    int base = dir * KK + row * KDIM;
    const float* b = ((dir == 0) ? g_B0 : g_B1) + row * KDIM;
    const float* G = (dir == 0) ? g_Ga : g_Gb;
    const float* m = g_mask + base;
    float* invM = g_invM + base;
    float* R = g_R + base;
    float* P = g_P + base;
    float* X = out + base;
    int t = threadIdx.x;
    float part = 0.f;
    #pragma unroll
    for (int q = 0; q < 2; q++) {
        int k = t + q * 256;
        float im = 1.f / (G[k * KDIM + k] + LMBDA * m[k]);
        float r = b[k];
        float zv = im * r;
        invM[k] = im; R[k] = r; P[k] = zv; X[k] = 0.f;
        __nv_bfloat16 s0, s1, s2;
        split3(zv, s0, s1, s2);
        g_Pb[base + k] = s0;
        g_Pb[2 * KK + base + k] = s1;
        g_Pb[4 * KK + base + k] = s2;
        part += r * zv;
    }
    float rz = blockReduce256(part, sh);
    if (t == 0) g_rz[blk] = rz;
}

// ---------------- K7: PCG update (folds 6 partials + diag term) ----------------
__global__ void __launch_bounds__(256) kupdate(float* __restrict__ out) {
    __shared__ float sh[8];
    int blk = blockIdx.x;
    int dir = blk >> 9, row = blk & 511;
    int base = dir * KK + row * KDIM;
    int prow = row * KDIM;
    float* P = g_P + base;
    float* R = g_R + base;
    float* X = out + base;
    const float* invM = g_invM + base;
    const float* M = g_mask + base;
    int t = threadIdx.x;
    int k0 = t, k1 = t + 256;

    float p0 = P[k0], p1 = P[k1];
    float s0 = LMBDA * M[k0] * p0;
    float s1 = LMBDA * M[k1] * p1;
    #pragma unroll
    for (int j = 0; j < 6; j++) {
        const float* Sp = g_Sp + (size_t)(j * 2 + dir) * KK + prow;
        s0 += Sp[k0];
        s1 += Sp[k1];
    }
    float ps = blockReduce256(p0 * s0 + p1 * s1, sh);
    float rz_old = g_rz[blk];
    float alpha = rz_old / fmaxf(ps, 1e-30f);

    float r0 = R[k0] - alpha * s0;
    float r1 = R[k1] - alpha * s1;
    X[k0] += alpha * p0;
    X[k1] += alpha * p1;
    float z0 = invM[k0] * r0, z1 = invM[k1] * r1;
    float rz = blockReduce256(r0 * z0 + r1 * z1, sh);
    float beta = rz / fmaxf(rz_old, 1e-30f);

    float pn0 = z0 + beta * p0;
    float pn1 = z1 + beta * p1;
    P[k0] = pn0; P[k1] = pn1;
    R[k0] = r0;  R[k1] = r1;

    __nv_bfloat16 a, b, c;
    split3(pn0, a, b, c);
    g_Pb[base + k0] = a; g_Pb[2 * KK + base + k0] = b; g_Pb[4 * KK + base + k0] = c;
    split3(pn1, a, b, c);
    g_Pb[base + k1] = a; g_Pb[2 * KK + base + k1] = b; g_Pb[4 * KK + base + k1] = c;

    if (t == 0) g_rz[blk] = rz;
}

// ---------------- launch ----------------
extern "C" void kernel_launch(void* const* d_in, const int* in_sizes, int n_in,
                              void* d_out, int out_size) {
    const float* A  = (const float*)d_in[0];
    const float* Bm = (const float*)d_in[1];
    const float* ea = (const float*)d_in[2];
    const float* eb = (const float*)d_in[3];
    float* out = (float*)d_out;

    const int DYN = 2 * 27648;  // 55.3 KB: 2 stages x (A 128x144B + B 64x144B)
    cudaFuncSetAttribute(gemm_mma, cudaFuncAttributeMaxDynamicSharedMemorySize, DYN);

    kmax<<<1, 256>>>(ea, eb);
    kmask<<<(2 * KK + 255) / 256, 256>>>(ea, eb);
    ktrs<<<dim3(16, 32, 2), 256>>>(A, Bm);
    gemm_mma<<<dim3(4, 8, 8), 256, DYN>>>(0);
    kfold<<<KK / 256, 256>>>();
    ktrB1<<<dim3(16, 16), 256>>>();
    ksplitG<<<(2 * KK + 255) / 256, 256>>>();
    kinit<<<1024, 256>>>(out);
    for (int it = 0; it < NITER; it++) {
        gemm_mma<<<dim3(4, 8, 12), 256, DYN>>>(1);
        kupdate<<<1024, 256>>>(out);
    }
}

// round 15
// speedup vs baseline: 1.2900x; 1.2900x over previous
#include <cuda_runtime.h>
#include <cuda_bf16.h>
#include <cstdint>

#define KDIM 512
#define DDIM 1024
#define KK (KDIM*KDIM)
#define KD (KDIM*DDIM)
#define LMBDA 1000.0f
#define NITER 18

// ---------------- device scratch ----------------
__device__ __align__(16) float g_Ga[KK];
__device__ __align__(16) float g_Gb[KK];
__device__ __align__(16) float g_B0[KK];
__device__ __align__(16) float g_B1[KK];
__device__ __align__(16) float g_mask[2*KK];
__device__ __align__(16) float g_invM[2*KK];
__device__ __align__(16) float g_R[2*KK];
__device__ __align__(16) float g_P[2*KK];
__device__ __align__(16) float g_S[2*KK];   // partial 0 (also phase0 scratch)
__device__ __align__(16) float g_S2[2*KK];  // partial 1 (also phase0 scratch)
__device__ __align__(16) float g_S3[2*KK];  // partial 2
__device__ float g_rz[2*KDIM];
__device__ float g_smax;
// bf16 3-way splits
__device__ __align__(16) __nv_bfloat16 g_Pb[3*2*KK];   // [split][dir][row][k]
__device__ __align__(16) __nv_bfloat16 g_G3[3*2*KK];   // [split][dir][n][k]
__device__ __align__(16) __nv_bfloat16 g_Xt[3*KD];     // [split][m=512][d=1024]
__device__ __align__(16) __nv_bfloat16 g_Yt[3*KD];

// split-product tables: (0,0),(0,1),(1,0),(1,1),(0,2),(2,0)
__constant__ int c_pa0[2][3] = {{0,0,1},{1,0,2}};
__constant__ int c_pb0[2][3] = {{0,1,0},{1,2,0}};
__constant__ int c_pa1[3][2] = {{0,0},{1,1},{0,2}};
__constant__ int c_pb1[3][2] = {{0,1},{0,1},{2,0}};

// ---------------- helpers ----------------
__device__ __forceinline__ uint32_t smem_u32(const void* p) {
    uint32_t a;
    asm("{ .reg .u64 t; cvta.to.shared.u64 t, %1; cvt.u32.u64 %0, t; }" : "=r"(a) : "l"(p));
    return a;
}
__device__ __forceinline__ void cp16(uint32_t dst, const void* src) {
    asm volatile("cp.async.cg.shared.global [%0], [%1], 16;" :: "r"(dst), "l"(src));
}
#define CP_COMMIT() asm volatile("cp.async.commit_group;" ::: "memory")
#define CP_WAIT2()  asm volatile("cp.async.wait_group 2;" ::: "memory")
#define CP_WAIT1()  asm volatile("cp.async.wait_group 1;" ::: "memory")
#define CP_WAIT0()  asm volatile("cp.async.wait_group 0;" ::: "memory")

__device__ __forceinline__ void ldm_x4(uint32_t* r, uint32_t addr) {
    asm volatile("ldmatrix.sync.aligned.m8n8.x4.shared.b16 {%0,%1,%2,%3}, [%4];"
        : "=r"(r[0]), "=r"(r[1]), "=r"(r[2]), "=r"(r[3]) : "r"(addr));
}
__device__ __forceinline__ void mma16816(float* d, const uint32_t* a, uint32_t b0, uint32_t b1) {
    asm volatile(
        "mma.sync.aligned.m16n8k16.row.col.f32.bf16.bf16.f32 "
        "{%0,%1,%2,%3}, {%4,%5,%6,%7}, {%8,%9}, {%0,%1,%2,%3};"
        : "+f"(d[0]), "+f"(d[1]), "+f"(d[2]), "+f"(d[3])
        : "r"(a[0]), "r"(a[1]), "r"(a[2]), "r"(a[3]), "r"(b0), "r"(b1));
}

__device__ __forceinline__ float blockReduce256(float v, float* sh) {
    #pragma unroll
    for (int o = 16; o > 0; o >>= 1) v += __shfl_xor_sync(0xffffffffu, v, o);
    int w = threadIdx.x >> 5;
    if ((threadIdx.x & 31) == 0) sh[w] = v;
    __syncthreads();
    if (threadIdx.x < 32) {
        float r = (threadIdx.x < 8) ? sh[threadIdx.x] : 0.f;
        #pragma unroll
        for (int o = 4; o > 0; o >>= 1) r += __shfl_xor_sync(0xffffffffu, r, o);
        if (threadIdx.x == 0) sh[0] = r;
    }
    __syncthreads();
    float out = sh[0];
    __syncthreads();
    return out;
}

__device__ __forceinline__ void split3(float x, __nv_bfloat16& a, __nv_bfloat16& b, __nv_bfloat16& c) {
    a = __float2bfloat16_rn(x);
    float r = x - __bfloat162float(a);
    b = __float2bfloat16_rn(r);
    r -= __bfloat162float(b);
    c = __float2bfloat16_rn(r);
}

// ---------------- K1: joint max eigenvalue ----------------
__global__ void kmax(const float* __restrict__ ea, const float* __restrict__ eb) {
    __shared__ float sm[256];
    int t = threadIdx.x;
    float m = 0.f;
    for (int i = t; i < KDIM; i += 256) { m = fmaxf(m, ea[i]); m = fmaxf(m, eb[i]); }
    sm[t] = m; __syncthreads();
    for (int s = 128; s > 0; s >>= 1) { if (t < s) sm[t] = fmaxf(sm[t], sm[t + s]); __syncthreads(); }
    if (t == 0) g_smax = sm[0];
}

// ---------------- K2: resolvent masks ----------------
__global__ void kmask(const float* __restrict__ ea, const float* __restrict__ eb) {
    int idx = blockIdx.x * blockDim.x + threadIdx.x;
    if (idx >= 2 * KK) return;
    int d = idx / KK;
    int rem = idx - d * KK;
    int r = rem >> 9, c = rem & (KDIM - 1);
    float s = g_smax;
    const float* er = (d == 0) ? eb : ea;
    const float* ec = (d == 0) ? ea : eb;
    float gb = er[r] / s, ga = ec[c] / s;
    float gb2 = gb * gb + 1.f, ga2 = ga * ga + 1.f;
    float mre = gb / gb2 - ga / ga2;
    float mim = 1.f / gb2 - 1.f / ga2;
    g_mask[idx] = mre * mre + mim * mim;
}

// ---------------- K3: transpose + 3-way split of descriptors ----------------
__global__ void __launch_bounds__(256) ktrs(const float* __restrict__ X,
                                            const float* __restrict__ Y) {
    const float* src = blockIdx.z ? Y : X;
    __nv_bfloat16* dst = blockIdx.z ? g_Yt : g_Xt;
    __shared__ float t[32][33];
    int c0 = blockIdx.x * 32, r0 = blockIdx.y * 32;
    int tx = threadIdx.x & 31, ty = threadIdx.x >> 5;
    #pragma unroll
    for (int i = 0; i < 32; i += 8)
        t[ty + i][tx] = src[(size_t)(r0 + ty + i) * KDIM + c0 + tx];
    __syncthreads();
    #pragma unroll
    for (int i = 0; i < 32; i += 8) {
        int m = c0 + ty + i;
        int dcol = r0 + tx;
        float v = t[tx][ty + i];
        __nv_bfloat16 a, b, c;
        split3(v, a, b, c);
        size_t o = (size_t)m * DDIM + dcol;
        dst[o] = a; dst[KD + o] = b; dst[2 * KD + o] = c;
    }
}

// ---------------- K4: bf16-split HMMA GEMM, 64x64 tiles, 128 thr, 4-stage ----------------
// phase 0: grid (8,8,8): z&3 -> output {Ga,Gb,B0,(B1 skipped)}, z>>2 -> 3-product half
//          K=3*1024; Ga/Gb upper-triangle tiles skipped (mirrored in kfold)
// phase 1: grid (8,8,6): z&1 -> dir, z>>1 -> 2-product slice; K=2*512; writes S/S2/S3
__global__ void __launch_bounds__(128) gemm_mma(int phase) {
    extern __shared__ __align__(16) uint8_t dynsm[];
    int tid = threadIdx.x, lane = tid & 31, warp = tid >> 5;
    int m0 = blockIdx.x * 64, n0 = blockIdx.y * 64, z = blockIdx.z;

    const __nv_bfloat16* Aseg[3];
    const __nv_bfloat16* Bseg[3];
    int ldk, nch, cpsh;
    float* Cp;
    if (phase == 0) {
        int outz = z & 3, h = z >> 2;
        if (outz == 3) return;                     // B1 = B0^T (ktrB1)
        if (outz < 2 && n0 > m0) return;           // symmetric: lower triangle only
        const __nv_bfloat16* L  = (outz == 0 || outz == 3) ? g_Xt : g_Yt;
        const __nv_bfloat16* Rt = (outz == 0 || outz == 2) ? g_Xt : g_Yt;
        #pragma unroll
        for (int s = 0; s < 3; s++) {
            Aseg[s] = L  + (size_t)c_pa0[h][s] * KD;
            Bseg[s] = Rt + (size_t)c_pb0[h][s] * KD;
        }
        ldk = DDIM; nch = 48; cpsh = 4;
        float* prim[4] = { g_Ga, g_Gb, g_B0, g_B1 };
        float* sec[4]  = { g_S, g_S + KK, g_S2, g_S2 + KK };
        Cp = h ? sec[outz] : prim[outz];
    } else {
        int dir = z & 1, h = z >> 1;
        #pragma unroll
        for (int s = 0; s < 2; s++) {
            Aseg[s] = g_Pb + (size_t)c_pa1[h][s] * 2 * KK + (size_t)dir * KK;
            Bseg[s] = g_G3 + (size_t)c_pb1[h][s] * 2 * KK + (size_t)dir * KK;
        }
        Aseg[2] = Aseg[0]; Bseg[2] = Bseg[0];
        ldk = KDIM; nch = 16; cpsh = 3;
        Cp = ((h == 0) ? g_S : (h == 1) ? g_S2 : g_S3) + (size_t)dir * KK;
    }

    uint32_t sb = smem_u32(dynsm);
    uint32_t aAdr[4] = { sb, sb + 9216u, sb + 18432u, sb + 27648u };
    uint32_t bAdr[4] = { sb + 36864u, sb + 46080u, sb + 55296u, sb + 64512u };

    int urow = tid >> 3;   // 0..15
    int uq = tid & 7;      // 16B unit in 128B row

    auto issue = [&](int c, int buf) {
        int seg = c >> cpsh;
        int koff = (c - (seg << cpsh)) * 64;
        const __nv_bfloat16* As = Aseg[seg];
        const __nv_bfloat16* Bs = Bseg[seg];
        #pragma unroll
        for (int j = 0; j < 4; j++) {
            int row = urow + j * 16;
            uint32_t so = (uint32_t)(row * 144 + uq * 16);
            cp16(aAdr[buf] + so, As + (size_t)(m0 + row) * ldk + koff + uq * 8);
            cp16(bAdr[buf] + so, Bs + (size_t)(n0 + row) * ldk + koff + uq * 8);
        }
        CP_COMMIT();
    };

    float acc[2][4][4] = {};
    int wm = (warp & 1) * 32, wn = (warp >> 1) * 32;
    int lrow = lane & 15, lhalf = lane >> 4;

    issue(0, 0);
    issue(1, 1);
    issue(2, 2);
    for (int c = 0; c < nch; c++) {
        int buf = c & 3;
        if (c >= nch - 1) CP_WAIT0();
        else if (c == nch - 2) CP_WAIT1();
        else CP_WAIT2();
        __syncthreads();
        if (c + 3 < nch) issue(c + 3, (c + 3) & 3);

        uint32_t aA = aAdr[buf] + (uint32_t)((wm + lrow) * 144 + lhalf * 16);
        uint32_t aB = bAdr[buf] + (uint32_t)((wn + lrow) * 144 + lhalf * 16);
        #pragma unroll
        for (int s = 0; s < 4; s++) {
            uint32_t a[2][4], bq[2][4];
            uint32_t ko = (uint32_t)(s * 32);
            ldm_x4(a[0],  aA + ko);
            ldm_x4(a[1],  aA + 16 * 144 + ko);
            ldm_x4(bq[0], aB + ko);
            ldm_x4(bq[1], aB + 16 * 144 + ko);
            #pragma unroll
            for (int mh = 0; mh < 2; mh++)
                #pragma unroll
                for (int nf = 0; nf < 4; nf++) {
                    int nh = nf >> 1, f = nf & 1;
                    mma16816(acc[mh][nf], a[mh], bq[nh][f], bq[nh][f + 2]);
                }
        }
    }

    // epilogue: pure store of partial tile
    int rr = m0 + wm + (lane >> 2);
    int cc0 = n0 + wn + (lane & 3) * 2;
    #pragma unroll
    for (int mh = 0; mh < 2; mh++) {
        #pragma unroll
        for (int nf = 0; nf < 4; nf++) {
            int r = rr + mh * 16;
            int cc = cc0 + nf * 8;
            *(float2*)&Cp[(size_t)r * KDIM + cc] =
                make_float2(acc[mh][nf][0], acc[mh][nf][1]);
            *(float2*)&Cp[(size_t)(r + 8) * KDIM + cc] =
                make_float2(acc[mh][nf][2], acc[mh][nf][3]);
        }
    }
}

// ---------------- K4b: fold phase-0 partials (Ga/Gb mirrored, B0 full) ----------------
__global__ void kfold() {
    int i = blockIdx.x * blockDim.x + threadIdx.x;
    if (i >= KK) return;
    int r = i >> 9, c = i & (KDIM - 1);
    if (r >= c) {
        float va = g_Ga[i] + g_S[i];
        float vb = g_Gb[i] + g_S[KK + i];
        int it = c * KDIM + r;
        g_Ga[i] = va; g_Ga[it] = va;
        g_Gb[i] = vb; g_Gb[it] = vb;
    }
    g_B0[i] += g_S2[i];
}

// ---------------- K4c: B1 = B0^T (tiled transpose) ----------------
__global__ void __launch_bounds__(256) ktrB1() {
    __shared__ float t[32][33];
    int c0 = blockIdx.x * 32, r0 = blockIdx.y * 32;
    int tx = threadIdx.x & 31, ty = threadIdx.x >> 5;
    #pragma unroll
    for (int i = 0; i < 32; i += 8)
        t[ty + i][tx] = g_B0[(size_t)(r0 + ty + i) * KDIM + c0 + tx];
    __syncthreads();
    #pragma unroll
    for (int i = 0; i < 32; i += 8)
        g_B1[(size_t)(c0 + ty + i) * KDIM + r0 + tx] = t[tx][ty + i];
}

// ---------------- K5: 3-way bf16 split of G ----------------
__global__ void ksplitG() {
    int idx = blockIdx.x * blockDim.x + threadIdx.x;
    if (idx >= 2 * KK) return;
    float v = (idx < KK) ? g_Ga[idx] : g_Gb[idx - KK];
    __nv_bfloat16 a, b, c;
    split3(v, a, b, c);
    g_G3[idx] = a;
    g_G3[2 * KK + idx] = b;
    g_G3[4 * KK + idx] = c;
}

// ---------------- K6: PCG init ----------------
__global__ void __launch_bounds__(256) kinit(float* __restrict__ out) {
    __shared__ float sh[8];
    int blk = blockIdx.x;
    int dir = blk >> 9, row = blk & 511;
    int base = dir * KK + row * KDIM;
    const float* b = ((dir == 0) ? g_B0 : g_B1) + row * KDIM;
    const float* G = (dir == 0) ? g_Ga : g_Gb;
    const float* m = g_mask + base;
    float* invM = g_invM + base;
    float* R = g_R + base;
    float* P = g_P + base;
    float* X = out + base;
    int t = threadIdx.x;
    float part = 0.f;
    #pragma unroll
    for (int q = 0; q < 2; q++) {
        int k = t + q * 256;
        float im = 1.f / (G[k * KDIM + k] + LMBDA * m[k]);
        float r = b[k];
        float zv = im * r;
        invM[k] = im; R[k] = r; P[k] = zv; X[k] = 0.f;
        __nv_bfloat16 s0, s1, s2;
        split3(zv, s0, s1, s2);
        g_Pb[base + k] = s0;
        g_Pb[2 * KK + base + k] = s1;
        g_Pb[4 * KK + base + k] = s2;
        part += r * zv;
    }
    float rz = blockReduce256(part, sh);
    if (t == 0) g_rz[blk] = rz;
}

// ---------------- K7: PCG update (folds 3 partials + diag term) ----------------
__global__ void __launch_bounds__(256) kupdate(float* __restrict__ out) {
    __shared__ float sh[8];
    int blk = blockIdx.x;
    int dir = blk >> 9, row = blk & 511;
    int base = dir * KK + row * KDIM;
    float* P = g_P + base;
    float* R = g_R + base;
    float* X = out + base;
    const float* invM = g_invM + base;
    const float* M = g_mask + base;
    int t = threadIdx.x;
    int k0 = t, k1 = t + 256;

    float p0 = P[k0], p1 = P[k1];
    float s0 = g_S[base + k0] + g_S2[base + k0] + g_S3[base + k0] + LMBDA * M[k0] * p0;
    float s1 = g_S[base + k1] + g_S2[base + k1] + g_S3[base + k1] + LMBDA * M[k1] * p1;
    float ps = blockReduce256(p0 * s0 + p1 * s1, sh);
    float rz_old = g_rz[blk];
    float alpha = rz_old / fmaxf(ps, 1e-30f);

    float r0 = R[k0] - alpha * s0;
    float r1 = R[k1] - alpha * s1;
    X[k0] += alpha * p0;
    X[k1] += alpha * p1;
    float z0 = invM[k0] * r0, z1 = invM[k1] * r1;
    float rz = blockReduce256(r0 * z0 + r1 * z1, sh);
    float beta = rz / fmaxf(rz_old, 1e-30f);

    float pn0 = z0 + beta * p0;
    float pn1 = z1 + beta * p1;
    P[k0] = pn0; P[k1] = pn1;
    R[k0] = r0;  R[k1] = r1;

    __nv_bfloat16 a, b, c;
    split3(pn0, a, b, c);
    g_Pb[base + k0] = a; g_Pb[2 * KK + base + k0] = b; g_Pb[4 * KK + base + k0] = c;
    split3(pn1, a, b, c);
    g_Pb[base + k1] = a; g_Pb[2 * KK + base + k1] = b; g_Pb[4 * KK + base + k1] = c;

    if (t == 0) g_rz[blk] = rz;
}

// ---------------- launch ----------------
extern "C" void kernel_launch(void* const* d_in, const int* in_sizes, int n_in,
                              void* d_out, int out_size) {
    const float* A  = (const float*)d_in[0];
    const float* Bm = (const float*)d_in[1];
    const float* ea = (const float*)d_in[2];
    const float* eb = (const float*)d_in[3];
    float* out = (float*)d_out;

    const int DYN = 8 * 9216;   // 72 KB: 4 stages x (A + B) 64x72 bf16 (144B rows)
    cudaFuncSetAttribute(gemm_mma, cudaFuncAttributeMaxDynamicSharedMemorySize, DYN);

    kmax<<<1, 256>>>(ea, eb);
    kmask<<<(2 * KK + 255) / 256, 256>>>(ea, eb);
    ktrs<<<dim3(16, 32, 2), 256>>>(A, Bm);
    gemm_mma<<<dim3(8, 8, 8), 128, DYN>>>(0);
    kfold<<<KK / 256, 256>>>();
    ktrB1<<<dim3(16, 16), 256>>>();
    ksplitG<<<(2 * KK + 255) / 256, 256>>>();
    kinit<<<1024, 256>>>(out);
    for (int it = 0; it < NITER; it++) {
        gemm_mma<<<dim3(8, 8, 6), 128, DYN>>>(1);
        kupdate<<<1024, 256>>>(out);
    }
}